// round 17
// baseline (speedup 1.0000x reference)
#include <cuda_runtime.h>
#include <cuda_bf16.h>
#include <cstdint>

#define DIM 128
#define DIM4 32
#define MAX_NODES 50000
#define MAX_EDGES 800000
#define CAP 96
#define EDGES_PER_BIN_BLOCK 512

#define TILE_M 128
#define KT 64            // k per phase (2 phases cover K=128)
#define SSTRIDE 72       // smem row stride in bf16 (bank-conflict-free)

// smem: Ahi, Alo, Bhi, Blo each 128 x SSTRIDE bf16 = 18432 B -> 73728 B total
#define SMEM_BYTES (4 * 128 * SSTRIDE * 2)

// ---- device scratch (allocation-free rule: __device__ globals; zero-init) --
__device__ float              g_HW[(size_t)MAX_NODES * DIM];
__device__ unsigned long long g_bin[(size_t)MAX_NODES * CAP];
__device__ int                g_cnt[MAX_NODES];
__device__ int                g_ovf_cnt;
__device__ int                g_done;                     // spmm completion counter
__device__ int                g_ovf_r[MAX_EDGES];
__device__ unsigned long long g_ovf_e[MAX_EDGES];

__device__ __forceinline__ uint32_t pack_bf16(__nv_bfloat16 a, __nv_bfloat16 b) {
    return (uint32_t)__bfloat16_as_ushort(a) | ((uint32_t)__bfloat16_as_ushort(b) << 16);
}

__device__ __forceinline__ void mma16816(float* d, uint32_t a0, uint32_t a1,
                                         uint32_t a2, uint32_t a3,
                                         uint32_t b0, uint32_t b1) {
    asm volatile(
        "mma.sync.aligned.m16n8k16.row.col.f32.bf16.bf16.f32 "
        "{%0,%1,%2,%3}, {%4,%5,%6,%7}, {%8,%9}, {%0,%1,%2,%3};"
        : "+f"(d[0]), "+f"(d[1]), "+f"(d[2]), "+f"(d[3])
        : "r"(a0), "r"(a1), "r"(a2), "r"(a3), "r"(b0), "r"(b1));
}

// ---------------------------------------------------------------------------
// Fused: blocks [0, ngb) = bf16x3 mma.sync GEMM tiles (128 rows x 128 cols),
//        converting W on the fly (L2-resident); blocks [ngb, ...) bin edges.
// ---------------------------------------------------------------------------
__global__ void __launch_bounds__(256, 2) fused_gemm_bin_kernel(
        const float* __restrict__ H, const float* __restrict__ W,
        const int* __restrict__ rows, const int* __restrict__ cols,
        const float* __restrict__ vals,
        int n_nodes, int n_edges, int n_gemm_blocks) {
    if ((int)blockIdx.x >= n_gemm_blocks) {
        // ---------------- bin path ----------------
        int base = ((int)blockIdx.x - n_gemm_blocks) * EDGES_PER_BIN_BLOCK
                 + (int)threadIdx.x;
#pragma unroll
        for (int t = 0; t < EDGES_PER_BIN_BLOCK / 256; t++) {
            int e = base + t * 256;
            if (e < n_edges) {
                int r = rows[e];
                unsigned long long pk = (unsigned long long)(unsigned)cols[e]
                    | ((unsigned long long)__float_as_uint(vals[e]) << 32);
                int p = atomicAdd(&g_cnt[r], 1);
                if (p < CAP) {
                    g_bin[(size_t)r * CAP + p] = pk;
                } else {
                    int q = atomicAdd(&g_ovf_cnt, 1);
                    g_ovf_r[q] = r;
                    g_ovf_e[q] = pk;
                }
            }
        }
        return;
    }

    // ---------------- GEMM path ----------------
    extern __shared__ char smem[];
    __nv_bfloat16* sAhi = (__nv_bfloat16*)smem;                 // [128][SSTRIDE]
    __nv_bfloat16* sAlo = sAhi + 128 * SSTRIDE;
    __nv_bfloat16* sBhi = sAlo + 128 * SSTRIDE;                 // [n][k]
    __nv_bfloat16* sBlo = sBhi + 128 * SSTRIDE;

    const int tid  = threadIdx.x;
    const int wid  = tid >> 5;
    const int lane = tid & 31;
    const int g    = lane >> 2;       // 0..7
    const int tg   = lane & 3;        // 0..3
    const int row0 = (int)blockIdx.x * TILE_M;

    // warp tile: rows r0..r0+31 (two 16-row tiles), cols c0..c0+63 (8 n-tiles)
    const int r0 = (wid & 3) * 32;
    const int c0 = (wid >> 2) * 64;

    float acc[2][8][4];
#pragma unroll
    for (int rt = 0; rt < 2; rt++)
#pragma unroll
        for (int nt = 0; nt < 8; nt++)
#pragma unroll
            for (int j = 0; j < 4; j++) acc[rt][nt][j] = 0.f;

    const float4* H4 = (const float4*)H;
    const float4* W4 = (const float4*)W;

    for (int p = 0; p < 2; p++) {
        __syncthreads();   // previous phase's fragment loads complete

        // A slice: H rows [row0, row0+128), k-half p -> bf16 hi/lo, padded
        for (int i = tid; i < 128 * (KT / 4); i += 256) {
            int r = i >> 4;
            int q = i & 15;
            int rr = row0 + r;
            float4 v = make_float4(0.f, 0.f, 0.f, 0.f);
            if (rr < n_nodes) v = H4[(size_t)rr * 32 + p * 16 + q];
            __nv_bfloat16 h0 = __float2bfloat16_rn(v.x);
            __nv_bfloat16 h1 = __float2bfloat16_rn(v.y);
            __nv_bfloat16 h2 = __float2bfloat16_rn(v.z);
            __nv_bfloat16 h3 = __float2bfloat16_rn(v.w);
            __nv_bfloat16 l0 = __float2bfloat16_rn(v.x - __bfloat162float(h0));
            __nv_bfloat16 l1 = __float2bfloat16_rn(v.y - __bfloat162float(h1));
            __nv_bfloat16 l2 = __float2bfloat16_rn(v.z - __bfloat162float(h2));
            __nv_bfloat16 l3 = __float2bfloat16_rn(v.w - __bfloat162float(h3));
            uint2* dh = (uint2*)&sAhi[r * SSTRIDE + q * 4];
            uint2* dl = (uint2*)&sAlo[r * SSTRIDE + q * 4];
            *dh = make_uint2(pack_bf16(h0, h1), pack_bf16(h2, h3));
            *dl = make_uint2(pack_bf16(l0, l1), pack_bf16(l2, l3));
        }
        // B slices from W on the fly: W[k][n] (k in phase) -> sB[n][k] hi/lo
        for (int i = tid; i < KT * DIM4; i += 256) {
            int k  = i >> 5;           // 0..63
            int q  = i & 31;           // float4 index over n
            float4 v = W4[(size_t)(p * KT + k) * DIM4 + q];
            int n0 = q * 4;
            __nv_bfloat16 h0 = __float2bfloat16_rn(v.x);
            __nv_bfloat16 h1 = __float2bfloat16_rn(v.y);
            __nv_bfloat16 h2 = __float2bfloat16_rn(v.z);
            __nv_bfloat16 h3 = __float2bfloat16_rn(v.w);
            sBhi[(n0 + 0) * SSTRIDE + k] = h0;
            sBhi[(n0 + 1) * SSTRIDE + k] = h1;
            sBhi[(n0 + 2) * SSTRIDE + k] = h2;
            sBhi[(n0 + 3) * SSTRIDE + k] = h3;
            sBlo[(n0 + 0) * SSTRIDE + k] = __float2bfloat16_rn(v.x - __bfloat162float(h0));
            sBlo[(n0 + 1) * SSTRIDE + k] = __float2bfloat16_rn(v.y - __bfloat162float(h1));
            sBlo[(n0 + 2) * SSTRIDE + k] = __float2bfloat16_rn(v.z - __bfloat162float(h2));
            sBlo[(n0 + 3) * SSTRIDE + k] = __float2bfloat16_rn(v.w - __bfloat162float(h3));
        }
        __syncthreads();

#pragma unroll
        for (int ks = 0; ks < KT / 16; ks++) {
            const int kk = ks * 16;
            uint32_t ah[2][4], al[2][4];
#pragma unroll
            for (int rt = 0; rt < 2; rt++) {
                int rb = r0 + rt * 16;
                ah[rt][0] = *(const uint32_t*)&sAhi[(rb + g)     * SSTRIDE + kk + 2 * tg];
                ah[rt][1] = *(const uint32_t*)&sAhi[(rb + g + 8) * SSTRIDE + kk + 2 * tg];
                ah[rt][2] = *(const uint32_t*)&sAhi[(rb + g)     * SSTRIDE + kk + 2 * tg + 8];
                ah[rt][3] = *(const uint32_t*)&sAhi[(rb + g + 8) * SSTRIDE + kk + 2 * tg + 8];
                al[rt][0] = *(const uint32_t*)&sAlo[(rb + g)     * SSTRIDE + kk + 2 * tg];
                al[rt][1] = *(const uint32_t*)&sAlo[(rb + g + 8) * SSTRIDE + kk + 2 * tg];
                al[rt][2] = *(const uint32_t*)&sAlo[(rb + g)     * SSTRIDE + kk + 2 * tg + 8];
                al[rt][3] = *(const uint32_t*)&sAlo[(rb + g + 8) * SSTRIDE + kk + 2 * tg + 8];
            }
#pragma unroll
            for (int nt = 0; nt < 8; nt++) {
                int n = c0 + nt * 8 + g;
                uint32_t bh0 = *(const uint32_t*)&sBhi[n * SSTRIDE + kk + 2 * tg];
                uint32_t bh1 = *(const uint32_t*)&sBhi[n * SSTRIDE + kk + 2 * tg + 8];
                uint32_t bl0 = *(const uint32_t*)&sBlo[n * SSTRIDE + kk + 2 * tg];
                uint32_t bl1 = *(const uint32_t*)&sBlo[n * SSTRIDE + kk + 2 * tg + 8];
#pragma unroll
                for (int rt = 0; rt < 2; rt++) {
                    mma16816(acc[rt][nt], ah[rt][0], ah[rt][1], ah[rt][2], ah[rt][3], bh0, bh1);
                    mma16816(acc[rt][nt], ah[rt][0], ah[rt][1], ah[rt][2], ah[rt][3], bl0, bl1);
                    mma16816(acc[rt][nt], al[rt][0], al[rt][1], al[rt][2], al[rt][3], bh0, bh1);
                }
            }
        }
    }

    // Epilogue: D rows (g, g+8), cols (2tg, 2tg+1) per tile; float2 stores
    float2* o = (float2*)g_HW;
#pragma unroll
    for (int rt = 0; rt < 2; rt++) {
#pragma unroll
        for (int nt = 0; nt < 8; nt++) {
            int col  = c0 + nt * 8 + 2 * tg;
            int rowA = row0 + r0 + rt * 16 + g;
            int rowB = rowA + 8;
            if (rowA < n_nodes)
                o[(size_t)rowA * 64 + (col >> 1)] = make_float2(acc[rt][nt][0], acc[rt][nt][1]);
            if (rowB < n_nodes)
                o[(size_t)rowB * 64 + (col >> 1)] = make_float2(acc[rt][nt][2], acc[rt][nt][3]);
        }
    }
}

// ---------------------------------------------------------------------------
// SpMM: one warp per output row (runs at the LTS cap). The LAST block to
// finish also drains the overflow list (all out writes visible via fences)
// and resets the counters for the next graph replay.
// ---------------------------------------------------------------------------
__global__ void __launch_bounds__(256) spmm_kernel(const float* __restrict__ bias,
                                                   float* __restrict__ out,
                                                   int n_nodes) {
    int gt   = blockIdx.x * blockDim.x + threadIdx.x;
    int r    = gt >> 5;
    int lane = gt & 31;

    if (r < n_nodes) {
        int cnt = g_cnt[r];
        if (lane == 0) g_cnt[r] = 0;   // self-clean for next replay
        int n = cnt > CAP ? CAP : cnt;
        const unsigned long long* bp = &g_bin[(size_t)r * CAP];

        float4 acc = ((const float4*)bias)[lane];
#pragma unroll 4
        for (int j = 0; j < n; j++) {
            unsigned long long e = bp[j];
            int   c = (int)(unsigned)e;
            float v = __uint_as_float((unsigned)(e >> 32));
            float4 hw = ((const float4*)g_HW)[(size_t)c * DIM4 + lane];
            acc.x += v * hw.x;
            acc.y += v * hw.y;
            acc.z += v * hw.z;
            acc.w += v * hw.w;
        }
        ((float4*)out)[(size_t)r * DIM4 + lane] = acc;
    }

    // ---- last-block overflow drain (canonical threadfence reduction form) --
    __shared__ int s_last;
    __threadfence();
    __syncthreads();
    if (threadIdx.x == 0) {
        int prev = atomicAdd(&g_done, 1);
        s_last = (prev == (int)gridDim.x - 1);
    }
    __syncthreads();
    if (s_last) {
        int n = g_ovf_cnt;
        if (n > 0) {
            int w    = threadIdx.x >> 5;
            int ln   = threadIdx.x & 31;
            for (int i = w; i < n; i += 8) {
                int rr = g_ovf_r[i];
                unsigned long long e = g_ovf_e[i];
                int   c = (int)(unsigned)e;
                float v = __uint_as_float((unsigned)(e >> 32));
                float4 hw = ((const float4*)g_HW)[(size_t)c * DIM4 + ln];
                float* pp = out + (size_t)rr * DIM + ln * 4;
                asm volatile("red.global.add.v4.f32 [%0], {%1, %2, %3, %4};"
                             :: "l"(pp), "f"(v * hw.x), "f"(v * hw.y),
                                "f"(v * hw.z), "f"(v * hw.w)
                             : "memory");
            }
        }
        __syncthreads();
        if (threadIdx.x == 0) { g_ovf_cnt = 0; g_done = 0; }
    }
}

// ---------------------------------------------------------------------------
// Launch. Inputs: edge_rows, edge_cols, edge_vals, H, W, bias. Output f32.
// ---------------------------------------------------------------------------
extern "C" void kernel_launch(void* const* d_in, const int* in_sizes, int n_in,
                              void* d_out, int out_size) {
    const int*   edge_rows = (const int*)d_in[0];
    const int*   edge_cols = (const int*)d_in[1];
    const float* edge_vals = (const float*)d_in[2];
    const float* H         = (const float*)d_in[3];
    const float* W         = (const float*)d_in[4];
    const float* bias      = (const float*)d_in[5];
    float*       out       = (float*)d_out;

    const int n_edges = in_sizes[0];
    const int n_nodes = in_sizes[3] / DIM;

    cudaFuncSetAttribute(fused_gemm_bin_kernel,
                         cudaFuncAttributeMaxDynamicSharedMemorySize, SMEM_BYTES);

    // 1) fused: tensor-core GEMM (W converted on the fly) + edge binning
    const int gemm_blocks = (n_nodes + TILE_M - 1) / TILE_M;
    const int bin_blocks  = (n_edges + EDGES_PER_BIN_BLOCK - 1) / EDGES_PER_BIN_BLOCK;
    fused_gemm_bin_kernel<<<gemm_blocks + bin_blocks, 256, SMEM_BYTES>>>(
        H, W, edge_rows, edge_cols, edge_vals, n_nodes, n_edges, gemm_blocks);

    // 2) out = bias + row-gathered sum; last block drains overflow + resets
    {
        long long threads = (long long)n_nodes * 32;
        spmm_kernel<<<(int)((threads + 255) / 256), 256>>>(bias, out, n_nodes);
    }
}